// round 12
// baseline (speedup 1.0000x reference)
#include <cuda_runtime.h>
#include <cuda_fp16.h>
#include <mma.h>
#include <cstddef>

using namespace nvcuda;

// Problem constants
#define S_LEN 256
#define T_LEN 256
#define BSZ   32
#define DIN   2048
#define HID   1024
#define G4    4096   // 4*HID

#define NBLK_REC 64    // recurrence blocks (barrier participants)
#define NBLK_GEMM 64   // embedded projection blocks

// Layer flag bases (monotonic within one kernel_launch; reset once per call)
#define BASE_L2 0u
#define BASE_L3 300u
#define BASE_L4 600u

// Scratch (device globals; allocation-free rule)
__device__ float g_xw[(size_t)S_LEN * BSZ * G4];     // proj buffer A (128 MiB)
__device__ float g_xw2[(size_t)S_LEN * BSZ * G4];    // proj buffer B (128 MiB)
__device__ float g_out2[(size_t)S_LEN * BSZ * HID];  // layer2 out (residual for L3)
__device__ float g_out3[(size_t)S_LEN * BSZ * HID];  // layer3 out (residual for L4)
__device__ __half g_outh[(size_t)S_LEN * BSZ * HID]; // masked out, fp16 (GEMM A)
__device__ __half g_h0[BSZ * HID];
__device__ __half g_h1[BSZ * HID];
__device__ __half g_ah[(size_t)S_LEN * BSZ * DIN];   // input slice fp16 (32 MiB)
__device__ __half g_wh[(size_t)G4 * DIN];            // Wih2 fp16 (16 MiB)

// Distributed barrier flags: one per rec block, 128B apart
__device__ unsigned g_flags[NBLK_REC * 32];

__device__ __forceinline__ unsigned ld_acq_(const unsigned* p) {
    unsigned v;
    asm volatile("ld.acquire.gpu.u32 %0, [%1];" : "=r"(v) : "l"(p) : "memory");
    return v;
}
__device__ __forceinline__ void st_rel_(unsigned* p, unsigned v) {
    asm volatile("st.release.gpu.u32 [%0], %1;" :: "l"(p), "r"(v) : "memory");
}

// One reset per kernel_launch call (first launch): replay-safe.
__global__ void reset_sync_kernel() {
    if (threadIdx.x < NBLK_REC) g_flags[threadIdx.x * 32] = 0u;
    __threadfence();
}

// Flag barrier: arrive = one release-store; wait = 64 threads poll 64 flags
// in parallel; block-wide agreement via __syncthreads_count.
__device__ __forceinline__ void grid_sync_(int bid, unsigned tval) {
    __syncthreads();
    if (threadIdx.x == 0) st_rel_(&g_flags[bid * 32], tval);
    unsigned pred;
    do {
        unsigned f = (threadIdx.x < NBLK_REC)
                   ? ld_acq_(&g_flags[threadIdx.x * 32]) : 0xFFFFFFFFu;
        pred = (f >= tval) ? 1u : 0u;
    } while (__syncthreads_count(pred) < blockDim.x);
}

// ---------------------------------------------------------------------------
// Header row
// ---------------------------------------------------------------------------
__global__ void header_kernel(float* __restrict__ out) {
    int i = blockIdx.x * blockDim.x + threadIdx.x;
    if (i < BSZ * HID) {
        float v = 0.f;
        if (i == 0) v = (float)(1 + S_LEN + T_LEN);
        else if (i == 1) v = (float)(S_LEN + 1);
        else if (i == 2) v = (float)(S_LEN + 2);
        else if (i == 3) v = (float)(T_LEN + S_LEN + 1);
        out[i] = v;
    }
}

// ---------------------------------------------------------------------------
// src_tgt copy
// ---------------------------------------------------------------------------
__global__ void copy_src_kernel(const float* __restrict__ in, float* __restrict__ out) {
    int l = blockIdx.x * blockDim.x + threadIdx.x;
    const int TOT = T_LEN * BSZ * (HID / 4);
    if (l < TOT) {
        int j4 = l % (HID / 4);
        int rb = l / (HID / 4);
        int b  = rb % BSZ;
        int i  = rb / BSZ;
        size_t in_off  = ((size_t)(1 + S_LEN + i) * BSZ + b) * DIN + (size_t)j4 * 4;
        size_t out_off = ((size_t)(1 + S_LEN + i) * BSZ + b) * HID + (size_t)j4 * 4;
        float4 v = *(const float4*)(in + in_off);
        *(float4*)(out + out_off) = v;
    }
}

// ---------------------------------------------------------------------------
// Dual fp32 -> fp16 bulk convert (two ranges in one kernel)
// ---------------------------------------------------------------------------
__global__ void f2h2_kernel(const float* __restrict__ a, __half* __restrict__ da,
                            int n4a,
                            const float* __restrict__ b, __half* __restrict__ db,
                            int n4b) {
    int i = blockIdx.x * blockDim.x + threadIdx.x;
    if (i < n4a) {
        float4 v = ((const float4*)a)[i];
        __half2* d = (__half2*)da + 2 * (size_t)i;
        d[0] = __floats2half2_rn(v.x, v.y);
        d[1] = __floats2half2_rn(v.z, v.w);
    } else if (i < n4a + n4b) {
        int k = i - n4a;
        float4 v = ((const float4*)b)[k];
        __half2* d = (__half2*)db + 2 * (size_t)k;
        d[0] = __floats2half2_rn(v.x, v.y);
        d[1] = __floats2half2_rn(v.z, v.w);
    }
}

// ---------------------------------------------------------------------------
// FP16-in GEMM-NT (fp32 accumulate): C[m,n] = sum_k A[m,k] * Bw[n,k]
// ---------------------------------------------------------------------------
#define ALD 40  // halves
__global__ void __launch_bounds__(256)
gemm_fp16h_kernel(const __half* __restrict__ A, const __half* __restrict__ Bw,
                  float* __restrict__ C, int M, int N, int K) {
    __shared__ __half As[128 * ALD];
    __shared__ __half Bs[128 * ALD];

    int tid = threadIdx.x;
    int bm = blockIdx.y * 128;
    int bn = blockIdx.x * 128;
    int warp = tid >> 5;
    int warpM = warp & 3;
    int warpN = warp >> 2;

    wmma::fragment<wmma::accumulator, 16, 16, 16, float> acc[2][4];
#pragma unroll
    for (int i = 0; i < 2; i++)
#pragma unroll
        for (int j = 0; j < 4; j++) wmma::fill_fragment(acc[i][j], 0.f);

    uint4 ra[2], rb[2];
#pragma unroll
    for (int v = 0; v < 2; v++) {
        int idx = v * 256 + tid;
        int row = idx >> 2;
        int c8 = (idx & 3) << 3;
        ra[v] = *(const uint4*)(A + (size_t)(bm + row) * K + c8);
        rb[v] = *(const uint4*)(Bw + (size_t)(bn + row) * K + c8);
    }

    for (int k0 = 0; k0 < K; k0 += 32) {
#pragma unroll
        for (int v = 0; v < 2; v++) {
            int idx = v * 256 + tid;
            int row = idx >> 2;
            int c8 = (idx & 3) << 3;
            *(uint4*)&As[row * ALD + c8] = ra[v];
            *(uint4*)&Bs[row * ALD + c8] = rb[v];
        }
        __syncthreads();

        if (k0 + 32 < K) {
#pragma unroll
            for (int v = 0; v < 2; v++) {
                int idx = v * 256 + tid;
                int row = idx >> 2;
                int c8 = (idx & 3) << 3;
                ra[v] = *(const uint4*)(A + (size_t)(bm + row) * K + k0 + 32 + c8);
                rb[v] = *(const uint4*)(Bw + (size_t)(bn + row) * K + k0 + 32 + c8);
            }
        }

#pragma unroll
        for (int kk = 0; kk < 32; kk += 16) {
            wmma::fragment<wmma::matrix_a, 16, 16, 16, __half, wmma::row_major> af[2];
            wmma::fragment<wmma::matrix_b, 16, 16, 16, __half, wmma::col_major> bf[4];
#pragma unroll
            for (int i = 0; i < 2; i++)
                wmma::load_matrix_sync(af[i], &As[(warpM * 32 + i * 16) * ALD + kk], ALD);
#pragma unroll
            for (int j = 0; j < 4; j++)
                wmma::load_matrix_sync(bf[j], &Bs[(warpN * 64 + j * 16) * ALD + kk], ALD);
#pragma unroll
            for (int i = 0; i < 2; i++)
#pragma unroll
                for (int j = 0; j < 4; j++)
                    wmma::mma_sync(acc[i][j], af[i], bf[j], acc[i][j]);
        }
        __syncthreads();
    }

#pragma unroll
    for (int i = 0; i < 2; i++)
#pragma unroll
        for (int j = 0; j < 4; j++) {
            float* cp = C + (size_t)(bm + warpM * 32 + i * 16) * N + bn + warpN * 64 + j * 16;
            wmma::store_matrix_sync(cp, acc[i][j], N, wmma::mem_row_major);
        }
}

// ---------------------------------------------------------------------------
// Fused layer kernel: blocks 0..63 = persistent LSTM recurrence
// (Whh fragments register-resident; WARP-LOCAL h staging: each warp stages
// only its own K-quarter, no block sync between stage and mma);
// blocks 64..127 = embedded projection GEMM behind the flag watermark.
// ---------------------------------------------------------------------------
#define WLD2 1032   // halves
#define HLD2 1032
#define GLD2 36     // floats
#define GSLAB (64 * GLD2)
#define SMEM_FUSED (64 * WLD2 * 2 + 128 * 72 * 2)
#define AGLD 72

__device__ __forceinline__ float sigmoidf_(float x) {
    return 1.0f / (1.0f + __expf(-x));
}

__global__ void __launch_bounds__(256, 1)
lstm_fused_kernel(const float* __restrict__ xw,     // (S,B,4H) this layer's proj
                  const float* __restrict__ Whh,    // (4H,H)
                  const float* __restrict__ bih,
                  const float* __restrict__ bhh,
                  const float* __restrict__ res,    // (S,B,H) or null
                  const float* __restrict__ maskp,  // (S,B,H) or null
                  float* __restrict__ out,          // (S,B,H)
                  __half* __restrict__ outm_h,      // (S,B,H) fp16 masked, or null
                  __half* __restrict__ h0,
                  __half* __restrict__ h1,
                  const float* __restrict__ WihN,   // next layer's Wih, or null
                  float* __restrict__ xw_next,      // next proj, or null
                  unsigned base)                    // layer flag base
{
    extern __shared__ char smraw[];
    const int tid = threadIdx.x;
    const int warp = tid >> 5;
    const int lane = tid & 31;

    if (blockIdx.x < NBLK_REC) {
        // ================= RECURRENCE ROLE =================
        __half* Wsh = (__half*)smraw;                    // [64][WLD2]  (init only)
        __half* Hs  = (__half*)smraw;                    // [32][HLD2]  (aliases Wsh)
        float*  Gs  = (float*)(smraw + 32 * HLD2 * 2);   // [4][64][GLD2]

        const int jbase = blockIdx.x * 16;
        const int Mt = warp & 1;      // 32-row group
        const int Ks = warp >> 1;     // K quarter (256 wide)
        const int kb = Ks * 256;

        // Load Whh slice -> fp16 smem. Local row r=g*16+u -> global g*HID+jbase+u
        for (int idx = tid; idx < 64 * 256; idx += 256) {
            int r = idx >> 8;
            int kq = (idx & 255) << 2;
            int grow = (r >> 4) * HID + jbase + (r & 15);
            float4 v = *(const float4*)(Whh + (size_t)grow * HID + kq);
            __half2* wp = (__half2*)&Wsh[r * WLD2 + kq];
            wp[0] = __floats2half2_rn(v.x, v.y);
            wp[1] = __floats2half2_rn(v.z, v.w);
        }
        __syncthreads();

        // Preload this warp's 32 Whh fragments into registers (persist all steps)
        wmma::fragment<wmma::matrix_a, 16, 16, 16, __half, wmma::row_major> afr[2][16];
#pragma unroll
        for (int m = 0; m < 2; m++)
#pragma unroll
            for (int kf = 0; kf < 16; kf++)
                wmma::load_matrix_sync(afr[m][kf],
                    &Wsh[(Mt * 32 + m * 16) * WLD2 + kb + kf * 16], WLD2);
        __syncthreads();   // Wsh region now dead -> reused as Hs/Gs

        // Zero initial h
        {
            __half* z = h0 + blockIdx.x * 512;
            z[tid] = __float2half(0.f);
            z[tid + 256] = __float2half(0.f);
        }

        const int u = tid & 15;
        const int bb = tid >> 4;      // 0..15
        const int j = jbase + u;
        float bias_[4];
#pragma unroll
        for (int g = 0; g < 4; g++)
            bias_[g] = bih[g * HID + j] + bhh[g * HID + j];
        float cc0 = 0.f, cc1 = 0.f;

        float xwc[4][2], resc[2] = {0.f, 0.f}, maskc[2] = {1.f, 1.f};
#pragma unroll
        for (int p = 0; p < 2; p++) {
            int b = bb + p * 16;
            const float* xwt = xw + (size_t)b * G4;
#pragma unroll
            for (int g = 0; g < 4; g++) xwc[g][p] = xwt[g * HID + j];
            if (res)   resc[p]  = res[(size_t)b * HID + j];
            if (maskp) maskc[p] = maskp[(size_t)b * HID + j];
        }

        // Initial barrier (h0 zeroing + Whh loads complete everywhere)
        grid_sync_(blockIdx.x, base + 1u);

        for (int t = 0; t < S_LEN; t++) {
            const __half* hin  = (t & 1) ? h1 : h0;
            __half*       hout = (t & 1) ? h0 : h1;

            // WARP-LOCAL staging: this warp stages Hs[b][kb..kb+256) for all 32
            // batches (its own mma K-slice). 32 uint4/lane, MLP-8 batches.
#pragma unroll
            for (int rr = 0; rr < 32; rr += 8) {
                uint4 x[8];
#pragma unroll
                for (int r = 0; r < 8; r++)
                    x[r] = __ldcg((const uint4*)(hin + (size_t)(rr + r) * HID + kb) + lane);
#pragma unroll
                for (int r = 0; r < 8; r++)
                    *(uint4*)&Hs[(rr + r) * HLD2 + kb + lane * 8] = x[r];
            }

            // Prefetch next step's xw / res / mask (latency hidden behind mma)
            float xwn[4][2] = {{0.f,0.f},{0.f,0.f},{0.f,0.f},{0.f,0.f}};
            float resn[2] = {0.f, 0.f}, maskn[2] = {1.f, 1.f};
            if (t + 1 < S_LEN) {
#pragma unroll
                for (int p = 0; p < 2; p++) {
                    int b = bb + p * 16;
                    const float* xwt = xw + ((size_t)(t + 1) * BSZ + b) * G4;
#pragma unroll
                    for (int g = 0; g < 4; g++) xwn[g][p] = xwt[g * HID + j];
                    if (res)   resn[p]  = res[((size_t)(t + 1) * BSZ + b) * HID + j];
                    if (maskp) maskn[p] = maskp[((size_t)(t + 1) * BSZ + b) * HID + j];
                }
            }
            __syncwarp();   // warp-local: own staging visible to own LDSM

            // Warp: 32 gate rows x 32 batches x 256 K. A from registers.
            wmma::fragment<wmma::accumulator, 16, 16, 16, float> acc[2][2];
#pragma unroll
            for (int m = 0; m < 2; m++)
#pragma unroll
                for (int n = 0; n < 2; n++) wmma::fill_fragment(acc[m][n], 0.f);

#pragma unroll
            for (int kf = 0; kf < 16; kf++) {
                wmma::fragment<wmma::matrix_b, 16, 16, 16, __half, wmma::col_major> b0, b1;
                wmma::load_matrix_sync(b0, Hs + kb + kf * 16, HLD2);
                wmma::load_matrix_sync(b1, Hs + 16 * HLD2 + kb + kf * 16, HLD2);
                wmma::mma_sync(acc[0][0], afr[0][kf], b0, acc[0][0]);
                wmma::mma_sync(acc[1][0], afr[1][kf], b0, acc[1][0]);
                wmma::mma_sync(acc[0][1], afr[0][kf], b1, acc[0][1]);
                wmma::mma_sync(acc[1][1], afr[1][kf], b1, acc[1][1]);
            }

#pragma unroll
            for (int m = 0; m < 2; m++)
#pragma unroll
                for (int n = 0; n < 2; n++)
                    wmma::store_matrix_sync(
                        &Gs[Ks * GSLAB + (Mt * 32 + m * 16) * GLD2 + n * 16],
                        acc[m][n], GLD2, wmma::mem_row_major);
            __syncthreads();

            // Cell update for both owned batches (sum 4 K-partial slabs)
#pragma unroll
            for (int p = 0; p < 2; p++) {
                int b = bb + p * 16;
                float gg4[4];
#pragma unroll
                for (int g = 0; g < 4; g++) {
                    float s = xwc[g][p] + bias_[g];
#pragma unroll
                    for (int sl = 0; sl < 4; sl++)
                        s += Gs[sl * GSLAB + (g * 16 + u) * GLD2 + b];
                    gg4[g] = s;
                }

                float ii = sigmoidf_(gg4[0]);
                float ff = sigmoidf_(gg4[1]);
                float gt = tanhf(gg4[2]);
                float oo = sigmoidf_(gg4[3]);

                float& cc = p ? cc1 : cc0;
                cc = ff * cc + ii * gt;
                float hn = oo * tanhf(cc);

                hout[(size_t)b * HID + j] = __float2half_rn(hn);
                float ov = hn + resc[p];
                size_t ooff = ((size_t)t * BSZ + b) * HID + j;
                out[ooff] = ov;
                if (outm_h) outm_h[ooff] = __float2half_rn(ov * maskc[p]);

#pragma unroll
                for (int g = 0; g < 4; g++) xwc[g][p] = xwn[g][p];
                resc[p] = resn[p];
                maskc[p] = maskn[p];
            }

            grid_sync_(blockIdx.x, base + (unsigned)(t + 2));
        }
    } else {
        // ================= EMBEDDED PROJECTION GEMM ROLE =================
        if (WihN == nullptr) return;
        __half* Bs = (__half*)smraw;                   // [64][WLD2] Wih strip
        __half* As = (__half*)(smraw + 64 * WLD2 * 2); // [128][AGLD]

        const int gblk = blockIdx.x - NBLK_REC;
        const int n0 = gblk * 64;
        const int Mw = warp & 3;
        const int Nw = warp >> 2;

        // Load Wih strip rows [n0, n0+64) fp32 -> fp16 smem
        for (int idx = tid; idx < 64 * 256; idx += 256) {
            int r = idx >> 8;
            int kq = (idx & 255) << 2;
            float4 v = *(const float4*)(WihN + (size_t)(n0 + r) * HID + kq);
            __half2* bp = (__half2*)&Bs[r * WLD2 + kq];
            bp[0] = __floats2half2_rn(v.x, v.y);
            bp[1] = __floats2half2_rn(v.z, v.w);
        }
        __syncthreads();

        for (int mt = 0; mt < 64; mt++) {
            // Wait until the 4 timesteps covering rows [mt*128, mt*128+128) are
            // done on ALL rec blocks: flag >= base + (mt+1)*4 + 1.
            {
                unsigned need = base + (unsigned)((mt + 1) * 4 + 1);
                unsigned pred;
                do {
                    unsigned f = (tid < NBLK_REC)
                               ? ld_acq_(&g_flags[tid * 32]) : 0xFFFFFFFFu;
                    pred = (f >= need) ? 1u : 0u;
                } while (__syncthreads_count(pred) < blockDim.x);
            }

            const int m0 = mt * 128;
            wmma::fragment<wmma::accumulator, 16, 16, 16, float> acc[2][2];
#pragma unroll
            for (int i = 0; i < 2; i++)
#pragma unroll
                for (int jj = 0; jj < 2; jj++) wmma::fill_fragment(acc[i][jj], 0.f);

            for (int k0 = 0; k0 < HID; k0 += 64) {
#pragma unroll
                for (int v = 0; v < 4; v++) {
                    int idx = v * 256 + tid;
                    int row = idx >> 3;
                    int c8 = (idx & 7) << 3;
                    *(uint4*)&As[row * AGLD + c8] =
                        __ldcg((const uint4*)(outm_h + (size_t)(m0 + row) * HID + k0 + c8));
                }
                __syncthreads();

#pragma unroll
                for (int kk = 0; kk < 64; kk += 16) {
                    wmma::fragment<wmma::matrix_a, 16, 16, 16, __half, wmma::row_major> af[2];
                    wmma::fragment<wmma::matrix_b, 16, 16, 16, __half, wmma::col_major> bf[2];
#pragma unroll
                    for (int i = 0; i < 2; i++)
                        wmma::load_matrix_sync(af[i], &As[(Mw * 32 + i * 16) * AGLD + kk], AGLD);
#pragma unroll
                    for (int jj = 0; jj < 2; jj++)
                        wmma::load_matrix_sync(bf[jj], &Bs[(Nw * 32 + jj * 16) * WLD2 + k0 + kk], WLD2);
#pragma unroll
                    for (int i = 0; i < 2; i++)
#pragma unroll
                        for (int jj = 0; jj < 2; jj++)
                            wmma::mma_sync(acc[i][jj], af[i], bf[jj], acc[i][jj]);
                }
                __syncthreads();
            }

#pragma unroll
            for (int i = 0; i < 2; i++)
#pragma unroll
                for (int jj = 0; jj < 2; jj++) {
                    float* cp = xw_next + (size_t)(m0 + Mw * 32 + i * 16) * G4
                              + n0 + Nw * 32 + jj * 16;
                    wmma::store_matrix_sync(cp, acc[i][jj], G4, wmma::mem_row_major);
                }
        }
    }
}

// ---------------------------------------------------------------------------
// Host launcher
// ---------------------------------------------------------------------------
extern "C" void kernel_launch(void* const* d_in, const int* in_sizes, int n_in,
                              void* d_out, int out_size) {
    const float* input = (const float*)d_in[0];
    const float* Wih2 = (const float*)d_in[1];
    const float* Whh2 = (const float*)d_in[2];
    const float* bih2 = (const float*)d_in[3];
    const float* bhh2 = (const float*)d_in[4];
    const float* Wih3 = (const float*)d_in[5];
    const float* Whh3 = (const float*)d_in[6];
    const float* bih3 = (const float*)d_in[7];
    const float* bhh3 = (const float*)d_in[8];
    const float* Wih4 = (const float*)d_in[9];
    const float* Whh4 = (const float*)d_in[10];
    const float* bih4 = (const float*)d_in[11];
    const float* bhh4 = (const float*)d_in[12];
    const float* mask2 = (const float*)d_in[13];
    const float* mask3 = (const float*)d_in[14];
    float* out = (float*)d_out;

    float *xw, *xw2, *out2, *out3;
    __half *outh, *h0, *h1, *ah, *wh;
    cudaGetSymbolAddress((void**)&xw, g_xw);
    cudaGetSymbolAddress((void**)&xw2, g_xw2);
    cudaGetSymbolAddress((void**)&out2, g_out2);
    cudaGetSymbolAddress((void**)&out3, g_out3);
    cudaGetSymbolAddress((void**)&outh, g_outh);
    cudaGetSymbolAddress((void**)&h0, g_h0);
    cudaGetSymbolAddress((void**)&h1, g_h1);
    cudaGetSymbolAddress((void**)&ah, g_ah);
    cudaGetSymbolAddress((void**)&wh, g_wh);

    cudaFuncSetAttribute(lstm_fused_kernel,
                         cudaFuncAttributeMaxDynamicSharedMemorySize, SMEM_FUSED);

    // (0) single epoch reset for this call (monotonic flags thereafter)
    reset_sync_kernel<<<1, 64>>>();
    // (1) header, (2) src_tgt copy
    header_kernel<<<(BSZ * HID + 255) / 256, 256>>>(out);
    copy_src_kernel<<<(T_LEN * BSZ * (HID / 4) + 255) / 256, 256>>>(input, out);
    // (3) both fp16 converts in one kernel
    {
        int nA4 = (S_LEN * BSZ * DIN) / 4;
        int nW4 = (G4 * DIN) / 4;
        f2h2_kernel<<<(nA4 + nW4 + 255) / 256, 256>>>(
            input + (size_t)BSZ * DIN, ah, nA4, Wih2, wh, nW4);
    }
    // (4) layer-2 projection: xw = ah @ wh^T
    dim3 ggrid(G4 / 128, (S_LEN * BSZ) / 128);
    gemm_fp16h_kernel<<<ggrid, 256>>>(ah, wh, xw, S_LEN * BSZ, G4, DIN);

    // (5) Layer 2: rec(xw) + embedded GEMM -> xw3 into g_xw2
    lstm_fused_kernel<<<NBLK_REC + NBLK_GEMM, 256, SMEM_FUSED>>>(
        xw, Whh2, bih2, bhh2,
        nullptr, mask2, out2, outh, h0, h1,
        Wih3, xw2, BASE_L2);

    // (6) Layer 3: rec(xw2) + embedded GEMM -> xw4 into g_xw
    lstm_fused_kernel<<<NBLK_REC + NBLK_GEMM, 256, SMEM_FUSED>>>(
        xw2, Whh3, bih3, bhh3,
        out2, mask3, out3, outh, h0, h1,
        Wih4, xw, BASE_L3);

    // (7) Layer 4: rec only -> rows [1, 1+S) of output
    lstm_fused_kernel<<<NBLK_REC, 256, SMEM_FUSED>>>(
        xw, Whh4, bih4, bhh4,
        out3, nullptr, out + (size_t)BSZ * HID, nullptr, h0, h1,
        nullptr, nullptr, BASE_L4);
}

// round 13
// speedup vs baseline: 1.1515x; 1.1515x over previous
#include <cuda_runtime.h>
#include <cuda_fp16.h>
#include <mma.h>
#include <cstddef>

using namespace nvcuda;

// Problem constants
#define S_LEN 256
#define T_LEN 256
#define BSZ   32
#define DIN   2048
#define HID   1024
#define G4    4096   // 4*HID

#define NBLK_REC 64    // recurrence blocks (barrier participants)
#define NBLK_GEMM 64   // embedded projection blocks

// Layer flag bases (monotonic within one kernel_launch; reset once per call)
#define BASE_L2 0u
#define BASE_L3 300u
#define BASE_L4 600u

// Scratch (device globals; allocation-free rule)
__device__ float g_xw[(size_t)S_LEN * BSZ * G4];     // proj buffer A (128 MiB)
__device__ float g_xw2[(size_t)S_LEN * BSZ * G4];    // proj buffer B (128 MiB)
__device__ float g_out2[(size_t)S_LEN * BSZ * HID];  // layer2 out (residual for L3)
__device__ float g_out3[(size_t)S_LEN * BSZ * HID];  // layer3 out (residual for L4)
__device__ __half g_outh[(size_t)S_LEN * BSZ * HID]; // masked out, fp16 (GEMM A)
__device__ __half g_h0[BSZ * HID];
__device__ __half g_h1[BSZ * HID];
__device__ __half g_ah[(size_t)S_LEN * BSZ * DIN];   // input slice fp16 (32 MiB)
__device__ __half g_wh[(size_t)G4 * DIN];            // Wih2 fp16 (16 MiB)

// Distributed barrier flags: one per rec block, 128B apart
__device__ unsigned g_flags[NBLK_REC * 32];

__device__ __forceinline__ unsigned ld_acq_(const unsigned* p) {
    unsigned v;
    asm volatile("ld.acquire.gpu.u32 %0, [%1];" : "=r"(v) : "l"(p) : "memory");
    return v;
}
__device__ __forceinline__ void st_rel_(unsigned* p, unsigned v) {
    asm volatile("st.release.gpu.u32 [%0], %1;" :: "l"(p), "r"(v) : "memory");
}

// One reset per kernel_launch call (first launch): replay-safe.
__global__ void reset_sync_kernel() {
    if (threadIdx.x < NBLK_REC) g_flags[threadIdx.x * 32] = 0u;
    __threadfence();
}

// Flag barrier: arrive = one release-store; wait = 64 threads poll 64 flags
// in parallel; block-wide agreement via __syncthreads_count.
__device__ __forceinline__ void grid_sync_(int bid, unsigned tval) {
    __syncthreads();
    if (threadIdx.x == 0) st_rel_(&g_flags[bid * 32], tval);
    unsigned pred;
    do {
        unsigned f = (threadIdx.x < NBLK_REC)
                   ? ld_acq_(&g_flags[threadIdx.x * 32]) : 0xFFFFFFFFu;
        pred = (f >= tval) ? 1u : 0u;
    } while (__syncthreads_count(pred) < blockDim.x);
}

// Fast saturating tanh / sigmoid (MUFU-based, no overflow path)
__device__ __forceinline__ float tanh_(float x) {
    float a = fabsf(x);
    float e = __expf(-2.f * a);                 // e in (0, 1]
    float t = __fdividef(1.f - e, 1.f + e);
    return copysignf(t, x);
}
__device__ __forceinline__ float sigmoidf_(float x) {
    return __fdividef(1.f, 1.f + __expf(-x));
}

// ---------------------------------------------------------------------------
// Header row
// ---------------------------------------------------------------------------
__global__ void header_kernel(float* __restrict__ out) {
    int i = blockIdx.x * blockDim.x + threadIdx.x;
    if (i < BSZ * HID) {
        float v = 0.f;
        if (i == 0) v = (float)(1 + S_LEN + T_LEN);
        else if (i == 1) v = (float)(S_LEN + 1);
        else if (i == 2) v = (float)(S_LEN + 2);
        else if (i == 3) v = (float)(T_LEN + S_LEN + 1);
        out[i] = v;
    }
}

// ---------------------------------------------------------------------------
// src_tgt copy
// ---------------------------------------------------------------------------
__global__ void copy_src_kernel(const float* __restrict__ in, float* __restrict__ out) {
    int l = blockIdx.x * blockDim.x + threadIdx.x;
    const int TOT = T_LEN * BSZ * (HID / 4);
    if (l < TOT) {
        int j4 = l % (HID / 4);
        int rb = l / (HID / 4);
        int b  = rb % BSZ;
        int i  = rb / BSZ;
        size_t in_off  = ((size_t)(1 + S_LEN + i) * BSZ + b) * DIN + (size_t)j4 * 4;
        size_t out_off = ((size_t)(1 + S_LEN + i) * BSZ + b) * HID + (size_t)j4 * 4;
        float4 v = *(const float4*)(in + in_off);
        *(float4*)(out + out_off) = v;
    }
}

// ---------------------------------------------------------------------------
// Dual fp32 -> fp16 bulk convert (two ranges in one kernel)
// ---------------------------------------------------------------------------
__global__ void f2h2_kernel(const float* __restrict__ a, __half* __restrict__ da,
                            int n4a,
                            const float* __restrict__ b, __half* __restrict__ db,
                            int n4b) {
    int i = blockIdx.x * blockDim.x + threadIdx.x;
    if (i < n4a) {
        float4 v = ((const float4*)a)[i];
        __half2* d = (__half2*)da + 2 * (size_t)i;
        d[0] = __floats2half2_rn(v.x, v.y);
        d[1] = __floats2half2_rn(v.z, v.w);
    } else if (i < n4a + n4b) {
        int k = i - n4a;
        float4 v = ((const float4*)b)[k];
        __half2* d = (__half2*)db + 2 * (size_t)k;
        d[0] = __floats2half2_rn(v.x, v.y);
        d[1] = __floats2half2_rn(v.z, v.w);
    }
}

// ---------------------------------------------------------------------------
// FP16-in GEMM-NT (fp32 accumulate): C[m,n] = sum_k A[m,k] * Bw[n,k]
// ---------------------------------------------------------------------------
#define ALD 40  // halves
__global__ void __launch_bounds__(256)
gemm_fp16h_kernel(const __half* __restrict__ A, const __half* __restrict__ Bw,
                  float* __restrict__ C, int M, int N, int K) {
    __shared__ __half As[128 * ALD];
    __shared__ __half Bs[128 * ALD];

    int tid = threadIdx.x;
    int bm = blockIdx.y * 128;
    int bn = blockIdx.x * 128;
    int warp = tid >> 5;
    int warpM = warp & 3;
    int warpN = warp >> 2;

    wmma::fragment<wmma::accumulator, 16, 16, 16, float> acc[2][4];
#pragma unroll
    for (int i = 0; i < 2; i++)
#pragma unroll
        for (int j = 0; j < 4; j++) wmma::fill_fragment(acc[i][j], 0.f);

    uint4 ra[2], rb[2];
#pragma unroll
    for (int v = 0; v < 2; v++) {
        int idx = v * 256 + tid;
        int row = idx >> 2;
        int c8 = (idx & 3) << 3;
        ra[v] = *(const uint4*)(A + (size_t)(bm + row) * K + c8);
        rb[v] = *(const uint4*)(Bw + (size_t)(bn + row) * K + c8);
    }

    for (int k0 = 0; k0 < K; k0 += 32) {
#pragma unroll
        for (int v = 0; v < 2; v++) {
            int idx = v * 256 + tid;
            int row = idx >> 2;
            int c8 = (idx & 3) << 3;
            *(uint4*)&As[row * ALD + c8] = ra[v];
            *(uint4*)&Bs[row * ALD + c8] = rb[v];
        }
        __syncthreads();

        if (k0 + 32 < K) {
#pragma unroll
            for (int v = 0; v < 2; v++) {
                int idx = v * 256 + tid;
                int row = idx >> 2;
                int c8 = (idx & 3) << 3;
                ra[v] = *(const uint4*)(A + (size_t)(bm + row) * K + k0 + 32 + c8);
                rb[v] = *(const uint4*)(Bw + (size_t)(bn + row) * K + k0 + 32 + c8);
            }
        }

#pragma unroll
        for (int kk = 0; kk < 32; kk += 16) {
            wmma::fragment<wmma::matrix_a, 16, 16, 16, __half, wmma::row_major> af[2];
            wmma::fragment<wmma::matrix_b, 16, 16, 16, __half, wmma::col_major> bf[4];
#pragma unroll
            for (int i = 0; i < 2; i++)
                wmma::load_matrix_sync(af[i], &As[(warpM * 32 + i * 16) * ALD + kk], ALD);
#pragma unroll
            for (int j = 0; j < 4; j++)
                wmma::load_matrix_sync(bf[j], &Bs[(warpN * 64 + j * 16) * ALD + kk], ALD);
#pragma unroll
            for (int i = 0; i < 2; i++)
#pragma unroll
                for (int j = 0; j < 4; j++)
                    wmma::mma_sync(acc[i][j], af[i], bf[j], acc[i][j]);
        }
        __syncthreads();
    }

#pragma unroll
    for (int i = 0; i < 2; i++)
#pragma unroll
        for (int j = 0; j < 4; j++) {
            float* cp = C + (size_t)(bm + warpM * 32 + i * 16) * N + bn + warpN * 64 + j * 16;
            wmma::store_matrix_sync(cp, acc[i][j], N, wmma::mem_row_major);
        }
}

// ---------------------------------------------------------------------------
// Fused layer kernel (proven R10 recurrence): blocks 0..63 = persistent LSTM
// (block-cooperative h staging; Whh fragments register-resident); blocks
// 64..127 = embedded projection GEMM behind the flag watermark.
// ---------------------------------------------------------------------------
#define WLD2 1032   // halves
#define HLD2 1032
#define GLD2 36     // floats
#define GSLAB (64 * GLD2)
#define SMEM_FUSED (64 * WLD2 * 2 + 128 * 72 * 2)
#define AGLD 72

__global__ void __launch_bounds__(256, 1)
lstm_fused_kernel(const float* __restrict__ xw,     // (S,B,4H) this layer's proj
                  const float* __restrict__ Whh,    // (4H,H)
                  const float* __restrict__ bih,
                  const float* __restrict__ bhh,
                  const float* __restrict__ res,    // (S,B,H) or null
                  const float* __restrict__ maskp,  // (S,B,H) or null
                  float* __restrict__ out,          // (S,B,H)
                  __half* __restrict__ outm_h,      // (S,B,H) fp16 masked, or null
                  __half* __restrict__ h0,
                  __half* __restrict__ h1,
                  const float* __restrict__ WihN,   // next layer's Wih, or null
                  float* __restrict__ xw_next,      // next proj, or null
                  unsigned base)                    // layer flag base
{
    extern __shared__ char smraw[];
    const int tid = threadIdx.x;
    const int warp = tid >> 5;

    if (blockIdx.x < NBLK_REC) {
        // ================= RECURRENCE ROLE =================
        __half* Wsh = (__half*)smraw;                    // [64][WLD2]  (init only)
        __half* Hs  = (__half*)smraw;                    // [32][HLD2]  (aliases Wsh)
        float*  Gs  = (float*)(smraw + 32 * HLD2 * 2);   // [4][64][GLD2]

        const int jbase = blockIdx.x * 16;
        const int Mt = warp & 1;      // 32-row group
        const int Ks = warp >> 1;     // K quarter (256 wide)
        const int kb = Ks * 256;

        // Load Whh slice -> fp16 smem. Local row r=g*16+u -> global g*HID+jbase+u
        for (int idx = tid; idx < 64 * 256; idx += 256) {
            int r = idx >> 8;
            int kq = (idx & 255) << 2;
            int grow = (r >> 4) * HID + jbase + (r & 15);
            float4 v = *(const float4*)(Whh + (size_t)grow * HID + kq);
            __half2* wp = (__half2*)&Wsh[r * WLD2 + kq];
            wp[0] = __floats2half2_rn(v.x, v.y);
            wp[1] = __floats2half2_rn(v.z, v.w);
        }
        __syncthreads();

        // Preload this warp's 32 Whh fragments into registers (persist all steps)
        wmma::fragment<wmma::matrix_a, 16, 16, 16, __half, wmma::row_major> afr[2][16];
#pragma unroll
        for (int m = 0; m < 2; m++)
#pragma unroll
            for (int kf = 0; kf < 16; kf++)
                wmma::load_matrix_sync(afr[m][kf],
                    &Wsh[(Mt * 32 + m * 16) * WLD2 + kb + kf * 16], WLD2);
        __syncthreads();   // Wsh region now dead -> reused as Hs/Gs

        // Zero initial h
        {
            __half* z = h0 + blockIdx.x * 512;
            z[tid] = __float2half(0.f);
            z[tid + 256] = __float2half(0.f);
        }

        const int u = tid & 15;
        const int bb = tid >> 4;      // 0..15
        const int j = jbase + u;
        float bias_[4];
#pragma unroll
        for (int g = 0; g < 4; g++)
            bias_[g] = bih[g * HID + j] + bhh[g * HID + j];
        float cc0 = 0.f, cc1 = 0.f;

        float xwc[4][2], resc[2] = {0.f, 0.f}, maskc[2] = {1.f, 1.f};
#pragma unroll
        for (int p = 0; p < 2; p++) {
            int b = bb + p * 16;
            const float* xwt = xw + (size_t)b * G4;
#pragma unroll
            for (int g = 0; g < 4; g++) xwc[g][p] = xwt[g * HID + j];
            if (res)   resc[p]  = res[(size_t)b * HID + j];
            if (maskp) maskc[p] = maskp[(size_t)b * HID + j];
        }

        // Initial barrier (h0 zeroing + Whh loads complete everywhere)
        grid_sync_(blockIdx.x, base + 1u);

        for (int t = 0; t < S_LEN; t++) {
            const __half* hin  = (t & 1) ? h1 : h0;
            __half*       hout = (t & 1) ? h0 : h1;

            // Stage full h (32x1024 fp16) via L2 (ldcg): block-cooperative
            {
                const uint4* hsrc = (const uint4*)hin;
#pragma unroll
                for (int v = 0; v < 16; v++) {
                    int i = v * 256 + tid;
                    int b = i >> 7;
                    int kq = (i & 127) << 3;
                    uint4 x = __ldcg(hsrc + i);
                    *(uint4*)&Hs[b * HLD2 + kq] = x;
                }
            }

            // Prefetch next step's xw / res / mask
            float xwn[4][2] = {{0.f,0.f},{0.f,0.f},{0.f,0.f},{0.f,0.f}};
            float resn[2] = {0.f, 0.f}, maskn[2] = {1.f, 1.f};
            if (t + 1 < S_LEN) {
#pragma unroll
                for (int p = 0; p < 2; p++) {
                    int b = bb + p * 16;
                    const float* xwt = xw + ((size_t)(t + 1) * BSZ + b) * G4;
#pragma unroll
                    for (int g = 0; g < 4; g++) xwn[g][p] = xwt[g * HID + j];
                    if (res)   resn[p]  = res[((size_t)(t + 1) * BSZ + b) * HID + j];
                    if (maskp) maskn[p] = maskp[((size_t)(t + 1) * BSZ + b) * HID + j];
                }
            }
            __syncthreads();

            // Warp: 32 gate rows x 32 batches x 256 K. A from registers.
            wmma::fragment<wmma::accumulator, 16, 16, 16, float> acc[2][2];
#pragma unroll
            for (int m = 0; m < 2; m++)
#pragma unroll
                for (int n = 0; n < 2; n++) wmma::fill_fragment(acc[m][n], 0.f);

#pragma unroll
            for (int kf = 0; kf < 16; kf++) {
                wmma::fragment<wmma::matrix_b, 16, 16, 16, __half, wmma::col_major> b0, b1;
                wmma::load_matrix_sync(b0, Hs + kb + kf * 16, HLD2);
                wmma::load_matrix_sync(b1, Hs + 16 * HLD2 + kb + kf * 16, HLD2);
                wmma::mma_sync(acc[0][0], afr[0][kf], b0, acc[0][0]);
                wmma::mma_sync(acc[1][0], afr[1][kf], b0, acc[1][0]);
                wmma::mma_sync(acc[0][1], afr[0][kf], b1, acc[0][1]);
                wmma::mma_sync(acc[1][1], afr[1][kf], b1, acc[1][1]);
            }

#pragma unroll
            for (int m = 0; m < 2; m++)
#pragma unroll
                for (int n = 0; n < 2; n++)
                    wmma::store_matrix_sync(
                        &Gs[Ks * GSLAB + (Mt * 32 + m * 16) * GLD2 + n * 16],
                        acc[m][n], GLD2, wmma::mem_row_major);
            __syncthreads();

            // Cell update for both owned batches (sum 4 K-partial slabs)
#pragma unroll
            for (int p = 0; p < 2; p++) {
                int b = bb + p * 16;
                float gg4[4];
#pragma unroll
                for (int g = 0; g < 4; g++) {
                    float s = xwc[g][p] + bias_[g];
#pragma unroll
                    for (int sl = 0; sl < 4; sl++)
                        s += Gs[sl * GSLAB + (g * 16 + u) * GLD2 + b];
                    gg4[g] = s;
                }

                float ii = sigmoidf_(gg4[0]);
                float ff = sigmoidf_(gg4[1]);
                float gt = tanh_(gg4[2]);
                float oo = sigmoidf_(gg4[3]);

                float& cc = p ? cc1 : cc0;
                cc = ff * cc + ii * gt;
                float hn = oo * tanh_(cc);

                hout[(size_t)b * HID + j] = __float2half_rn(hn);
                float ov = hn + resc[p];
                size_t ooff = ((size_t)t * BSZ + b) * HID + j;
                out[ooff] = ov;
                if (outm_h) outm_h[ooff] = __float2half_rn(ov * maskc[p]);

#pragma unroll
                for (int g = 0; g < 4; g++) xwc[g][p] = xwn[g][p];
                resc[p] = resn[p];
                maskc[p] = maskn[p];
            }

            grid_sync_(blockIdx.x, base + (unsigned)(t + 2));
        }
    } else {
        // ================= EMBEDDED PROJECTION GEMM ROLE =================
        if (WihN == nullptr) return;
        __half* Bs = (__half*)smraw;                   // [64][WLD2] Wih strip
        __half* As = (__half*)(smraw + 64 * WLD2 * 2); // [128][AGLD]

        const int gblk = blockIdx.x - NBLK_REC;
        const int n0 = gblk * 64;
        const int Mw = warp & 3;
        const int Nw = warp >> 2;

        // Load Wih strip rows [n0, n0+64) fp32 -> fp16 smem
        for (int idx = tid; idx < 64 * 256; idx += 256) {
            int r = idx >> 8;
            int kq = (idx & 255) << 2;
            float4 v = *(const float4*)(WihN + (size_t)(n0 + r) * HID + kq);
            __half2* bp = (__half2*)&Bs[r * WLD2 + kq];
            bp[0] = __floats2half2_rn(v.x, v.y);
            bp[1] = __floats2half2_rn(v.z, v.w);
        }
        __syncthreads();

        for (int mt = 0; mt < 64; mt++) {
            // Wait until the 4 timesteps covering rows [mt*128, mt*128+128) are
            // done on ALL rec blocks: flag >= base + (mt+1)*4 + 1.
            {
                unsigned need = base + (unsigned)((mt + 1) * 4 + 1);
                unsigned pred;
                do {
                    unsigned f = (tid < NBLK_REC)
                               ? ld_acq_(&g_flags[tid * 32]) : 0xFFFFFFFFu;
                    pred = (f >= need) ? 1u : 0u;
                } while (__syncthreads_count(pred) < blockDim.x);
            }

            const int m0 = mt * 128;
            wmma::fragment<wmma::accumulator, 16, 16, 16, float> acc[2][2];
#pragma unroll
            for (int i = 0; i < 2; i++)
#pragma unroll
                for (int jj = 0; jj < 2; jj++) wmma::fill_fragment(acc[i][jj], 0.f);

            for (int k0 = 0; k0 < HID; k0 += 64) {
#pragma unroll
                for (int v = 0; v < 4; v++) {
                    int idx = v * 256 + tid;
                    int row = idx >> 3;
                    int c8 = (idx & 7) << 3;
                    *(uint4*)&As[row * AGLD + c8] =
                        __ldcg((const uint4*)(outm_h + (size_t)(m0 + row) * HID + k0 + c8));
                }
                __syncthreads();

#pragma unroll
                for (int kk = 0; kk < 64; kk += 16) {
                    wmma::fragment<wmma::matrix_a, 16, 16, 16, __half, wmma::row_major> af[2];
                    wmma::fragment<wmma::matrix_b, 16, 16, 16, __half, wmma::col_major> bf[2];
#pragma unroll
                    for (int i = 0; i < 2; i++)
                        wmma::load_matrix_sync(af[i], &As[(Mw * 32 + i * 16) * AGLD + kk], AGLD);
#pragma unroll
                    for (int jj = 0; jj < 2; jj++)
                        wmma::load_matrix_sync(bf[jj], &Bs[(Nw * 32 + jj * 16) * WLD2 + k0 + kk], WLD2);
#pragma unroll
                    for (int i = 0; i < 2; i++)
#pragma unroll
                        for (int jj = 0; jj < 2; jj++)
                            wmma::mma_sync(acc[i][jj], af[i], bf[jj], acc[i][jj]);
                }
                __syncthreads();
            }

#pragma unroll
            for (int i = 0; i < 2; i++)
#pragma unroll
                for (int jj = 0; jj < 2; jj++) {
                    float* cp = xw_next + (size_t)(m0 + Mw * 32 + i * 16) * G4
                              + n0 + Nw * 32 + jj * 16;
                    wmma::store_matrix_sync(cp, acc[i][jj], G4, wmma::mem_row_major);
                }
        }
    }
}

// ---------------------------------------------------------------------------
// Host launcher
// ---------------------------------------------------------------------------
extern "C" void kernel_launch(void* const* d_in, const int* in_sizes, int n_in,
                              void* d_out, int out_size) {
    const float* input = (const float*)d_in[0];
    const float* Wih2 = (const float*)d_in[1];
    const float* Whh2 = (const float*)d_in[2];
    const float* bih2 = (const float*)d_in[3];
    const float* bhh2 = (const float*)d_in[4];
    const float* Wih3 = (const float*)d_in[5];
    const float* Whh3 = (const float*)d_in[6];
    const float* bih3 = (const float*)d_in[7];
    const float* bhh3 = (const float*)d_in[8];
    const float* Wih4 = (const float*)d_in[9];
    const float* Whh4 = (const float*)d_in[10];
    const float* bih4 = (const float*)d_in[11];
    const float* bhh4 = (const float*)d_in[12];
    const float* mask2 = (const float*)d_in[13];
    const float* mask3 = (const float*)d_in[14];
    float* out = (float*)d_out;

    float *xw, *xw2, *out2, *out3;
    __half *outh, *h0, *h1, *ah, *wh;
    cudaGetSymbolAddress((void**)&xw, g_xw);
    cudaGetSymbolAddress((void**)&xw2, g_xw2);
    cudaGetSymbolAddress((void**)&out2, g_out2);
    cudaGetSymbolAddress((void**)&out3, g_out3);
    cudaGetSymbolAddress((void**)&outh, g_outh);
    cudaGetSymbolAddress((void**)&h0, g_h0);
    cudaGetSymbolAddress((void**)&h1, g_h1);
    cudaGetSymbolAddress((void**)&ah, g_ah);
    cudaGetSymbolAddress((void**)&wh, g_wh);

    cudaFuncSetAttribute(lstm_fused_kernel,
                         cudaFuncAttributeMaxDynamicSharedMemorySize, SMEM_FUSED);

    // (0) single epoch reset for this call (monotonic flags thereafter)
    reset_sync_kernel<<<1, 64>>>();
    // (1) header, (2) src_tgt copy
    header_kernel<<<(BSZ * HID + 255) / 256, 256>>>(out);
    copy_src_kernel<<<(T_LEN * BSZ * (HID / 4) + 255) / 256, 256>>>(input, out);
    // (3) both fp16 converts in one kernel
    {
        int nA4 = (S_LEN * BSZ * DIN) / 4;
        int nW4 = (G4 * DIN) / 4;
        f2h2_kernel<<<(nA4 + nW4 + 255) / 256, 256>>>(
            input + (size_t)BSZ * DIN, ah, nA4, Wih2, wh, nW4);
    }
    // (4) layer-2 projection: xw = ah @ wh^T
    dim3 ggrid(G4 / 128, (S_LEN * BSZ) / 128);
    gemm_fp16h_kernel<<<ggrid, 256>>>(ah, wh, xw, S_LEN * BSZ, G4, DIN);

    // (5) Layer 2: rec(xw) + embedded GEMM -> xw3 into g_xw2
    lstm_fused_kernel<<<NBLK_REC + NBLK_GEMM, 256, SMEM_FUSED>>>(
        xw, Whh2, bih2, bhh2,
        nullptr, mask2, out2, outh, h0, h1,
        Wih3, xw2, BASE_L2);

    // (6) Layer 3: rec(xw2) + embedded GEMM -> xw4 into g_xw
    lstm_fused_kernel<<<NBLK_REC + NBLK_GEMM, 256, SMEM_FUSED>>>(
        xw2, Whh3, bih3, bhh3,
        out2, mask3, out3, outh, h0, h1,
        Wih4, xw, BASE_L3);

    // (7) Layer 4: rec only -> rows [1, 1+S) of output
    lstm_fused_kernel<<<NBLK_REC, 256, SMEM_FUSED>>>(
        xw, Whh4, bih4, bhh4,
        out3, nullptr, out + (size_t)BSZ * HID, nullptr, h0, h1,
        nullptr, nullptr, BASE_L4);
}